// round 13
// baseline (speedup 1.0000x reference)
#include <cuda_runtime.h>
#include <math.h>

// Problem constants
#define O_DIM 32
#define I_DIM 32
#define K_DIM 13
#define N_DIM 4096
#define IK    (I_DIM * K_DIM)    // 416
#define WSIZE (O_DIM * IK)       // 13312 floats = 53 KB

#define THREADS 512              // 16 warps; warp w owns o = 2w, 2w+1
#define BLOCKS  608              // 152 SMs * 4 resident blocks (all co-resident)

// Transposed x: xT[n][i] = x[i][n]  (4096 x 32 floats = 512 KB, L2-resident)
__device__ float xT[N_DIM * I_DIM];
// Grid-barrier epoch counter (monotonic across graph replays)
__device__ unsigned int g_bar;

__global__ void __launch_bounds__(THREADS, 4) plaq_kernel(
    const float* __restrict__ x,       // (I, N)
    const float* __restrict__ W,       // (O, I, K)
    const float* __restrict__ b,       // (O,)
    const float* __restrict__ mask,    // (N, O, I, K)
    const int*   __restrict__ shifts,  // (N, K)
    float*       __restrict__ out)     // (O, N)
{
    __shared__ float Wsh[WSIZE];
    __shared__ float gsh[2][IK];

    const int tid  = threadIdx.x;
    const int warp = tid >> 5;
    const int lane = tid & 31;
    const int bid  = blockIdx.x;

    // ---- Phase 1: in-kernel transpose (blocks 0..127, one 32x32 tile each).
    // Tile buffer aliases the head of Wsh (Wsh is written only after this phase).
    {
        float (*tile)[33] = (float(*)[33])Wsh;
        if (bid < N_DIM / 32) {
            const int n0t = bid * 32;
            #pragma unroll
            for (int r = warp; r < 32; r += 16)
                tile[r][lane] = x[r * N_DIM + n0t + lane];
            __syncthreads();
            #pragma unroll
            for (int r = warp; r < 32; r += 16)
                xT[(n0t + r) * I_DIM + lane] = tile[lane][r];
            __threadfence();               // publish xT before arriving
        }
        __syncthreads();                   // tile reads done before Wsh overwrite
    }

    // ---- Phase 2: load W into shared (overlaps other blocks' transpose work)
    #pragma unroll
    for (int e = tid; e < WSIZE; e += THREADS)
        Wsh[e] = W[e];
    __syncthreads();

    // ---- Phase 3: software grid barrier (replay-safe epoch arithmetic)
    if (tid == 0) {
        const unsigned old    = atomicAdd(&g_bar, 1u);
        const unsigned target = (old / BLOCKS + 1u) * BLOCKS;
        while (atomicAdd(&g_bar, 0u) < target)
            __nanosleep(64);
    }
    __syncthreads();

    const int o0 = warp * 2;
    const int o1 = o0 + 1;
    const float bias0 = b[o0];
    const float bias1 = b[o1];
    const float e_const = 2.718281828459045f;
    const float scale = (2.0f + 2.0f * e_const) / (e_const - 1.0f);
    const float* __restrict__ w0 = Wsh + o0 * IK;
    const float* __restrict__ w1 = Wsh + o1 * IK;

    // Prime buffer 0 with n = bid's gather: warp k (k<13) loads one xT row
    if (warp < K_DIM) {
        const int s = shifts[bid * K_DIM + warp];      // broadcast load
        gsh[0][lane * K_DIM + warp] = xT[s * I_DIM + lane];
    }
    __syncthreads();

    // ---- Phase 4: main loop, one n per iteration, ONE barrier each.
    int p = 0;
    for (int n = bid; n < N_DIM; n += BLOCKS) {
        // Dot: 26 coalesced scalar mask LDGs per warp (13 per o-row; the two
        // rows are adjacent, spanning 832 contiguous floats)
        const float* __restrict__ mrow = mask + ((size_t)n * O_DIM + o0) * IK;
        const float* __restrict__ g = gsh[p];

        float s0 = 0.0f, s1 = 0.0f;
        #pragma unroll
        for (int j = 0; j < K_DIM; ++j) {
            const int e = j * 32 + lane;     // 13*32 == 416 exactly
            const float gv = g[e];
            s0 += mrow[e]      * w0[e] * gv;
            s1 += mrow[IK + e] * w1[e] * gv;
        }

        // Keep the gather below from hoisting above the mask loads (R7/R10:
        // front-issued gathers steal L1tex priority from the stream)
        asm volatile("" ::: "memory");

        // Post-dot gather for the next n; latency hides under the
        // reduction + out-write + barrier window.
        const int nn = n + BLOCKS;
        if (warp < K_DIM && nn < N_DIM) {
            const int s = shifts[nn * K_DIM + warp];
            gsh[p ^ 1][lane * K_DIM + warp] = xT[s * I_DIM + lane];
        }

        // Warp reductions
        #pragma unroll
        for (int off = 16; off > 0; off >>= 1) {
            s0 += __shfl_xor_sync(0xffffffffu, s0, off);
            s1 += __shfl_xor_sync(0xffffffffu, s1, off);
        }

        if (lane == 0) {
            const float y0 = s0 + bias0;
            const float y1 = s1 + bias1;
            out[o0 * N_DIM + n] = (1.0f / (1.0f + __expf(-y0)) - 0.5f) * scale;
            out[o1 * N_DIM + n] = (1.0f / (1.0f + __expf(-y1)) - 0.5f) * scale;
        }

        __syncthreads();   // publishes gsh[p^1]; protects gsh[p] for next refill
        p ^= 1;
    }
}

extern "C" void kernel_launch(void* const* d_in, const int* in_sizes, int n_in,
                              void* d_out, int out_size) {
    const float* x      = (const float*)d_in[0];
    const float* Wconv  = (const float*)d_in[1];
    const float* bconv  = (const float*)d_in[2];
    const float* mask   = (const float*)d_in[3];
    const int*   shifts = (const int*)d_in[4];
    float* out          = (float*)d_out;

    plaq_kernel<<<BLOCKS, THREADS>>>(x, Wconv, bconv, mask, shifts, out);
}